// round 11
// baseline (speedup 1.0000x reference)
#include <cuda_runtime.h>
#include <cuda_fp16.h>
#include <cstdint>

// Problem dims (fixed by dataset)
#define HD    4096
#define MDIM  11008
#define TOK   512

__constant__ float NF4c[16] = {
    -1.0f, -0.6961928009986877f, -0.5250730514526367f, -0.39491748809814453f,
    -0.28444138169288635f, -0.18477343022823334f, -0.09105003625154495f, 0.0f,
    0.07958029955625534f, 0.16093020141124725f, 0.24611230194568634f,
    0.33791524171829224f, 0.44070982933044434f, 0.5626170039176941f,
    0.7229568362236023f, 1.0f};

// Static device scratch
__device__ __half g_wg[(size_t)MDIM * HD];   // gate W fp16, B-frag permuted
__device__ __half g_wu[(size_t)MDIM * HD];   // up   W fp16, B-frag permuted
__device__ __half g_wd[(size_t)HD * MDIM];   // down W fp16, B-frag permuted
__device__ __half g_xq[(size_t)TOK * HD];    // x fp16, A-frag permuted
__device__ __half g_hp[(size_t)TOK * MDIM];  // h fp16, A-frag permuted

__device__ __forceinline__ void cpa16(uint32_t dst, const void* src) {
    asm volatile("cp.async.cg.shared.global [%0], [%1], 16;" :: "r"(dst), "l"(src));
}
__device__ __forceinline__ uint32_t smem_u32(const void* p) {
    uint32_t a;
    asm("{ .reg .u64 t; cvta.to.shared.u64 t, %1; cvt.u32.u64 %0, t; }" : "=r"(a) : "l"(p));
    return a;
}
__device__ __forceinline__ uint32_t f2h2(float lo, float hi) {
    uint32_t r;
    asm("cvt.rn.f16x2.f32 %0, %2, %1;" : "=r"(r) : "f"(lo), "f"(hi));
    return r;
}
#define MMA_H(acc, a, b0, b1) \
    asm volatile( \
        "mma.sync.aligned.m16n8k16.row.col.f32.f16.f16.f32 " \
        "{%0,%1,%2,%3}, {%4,%5,%6,%7}, {%8,%9}, {%0,%1,%2,%3};" \
        : "+f"(acc[0]), "+f"(acc[1]), "+f"(acc[2]), "+f"(acc[3]) \
        : "r"(a[0]), "r"(a[1]), "r"(a[2]), "r"(a[3]), "r"(b0), "r"(b1))

#define CPA_WAIT(N) asm volatile("cp.async.wait_group %0;" :: "n"(N) : "memory")

// ---------------- permute x -> fp16 A-fragment layout ----------------
__global__ void permute_xh(const float* __restrict__ X, __half* __restrict__ Xp, int T, int K) {
    int gw = (blockIdx.x * blockDim.x + threadIdx.x) >> 5;
    int lane = threadIdx.x & 31;
    int kb16 = K >> 4;
    if (gw >= (T >> 4) * kb16) return;
    int tb = gw / kb16, kb = gw % kb16;
    int tg = lane >> 2, tig = lane & 3;
    const float* p0 = X + (size_t)(tb * 16 + tg) * K + kb * 16 + tig * 2;
    const float* p1 = p0 + (size_t)8 * K;
    float2 v00 = *(const float2*)p0;
    float2 v10 = *(const float2*)p1;
    float2 v01 = *(const float2*)(p0 + 8);
    float2 v11 = *(const float2*)(p1 + 8);
    uint4 o;
    o.x = f2h2(v00.x, v00.y);
    o.y = f2h2(v10.x, v10.y);
    o.z = f2h2(v01.x, v01.y);
    o.w = f2h2(v11.x, v11.y);
    *(uint4*)(Xp + ((size_t)gw * 32 + lane) * 8) = o;
}

// ---------------- dequant NF4 int32 codes -> fp16 W in B-frag layout ----------------
__device__ __forceinline__ void dequant_body(
    const int* __restrict__ codes, const float* __restrict__ absmax,
    __half* __restrict__ Wp, int M, int K, int gw, int lane, const float* Lut)
{
    int Kb64 = K >> 6, Kb16 = K >> 4;
    if (gw >= (M >> 3) * Kb64) return;
    int nb = gw / Kb64, kb64 = gw % Kb64;
    int n = lane >> 2, tig = lane & 3;
    int m = nb * 8 + n;
    float am = absmax[(size_t)m * Kb64 + kb64];
    const int* rp = codes + (size_t)m * K + (size_t)kb64 * 64;
#pragma unroll
    for (int q = 0; q < 4; q++) {
        int2 lo = *(const int2*)(rp + q * 16 + tig * 2);
        int2 hi = *(const int2*)(rp + q * 16 + tig * 2 + 8);
        uint2 o;
        o.x = f2h2(Lut[(lo.x << 5) + lane] * am, Lut[(lo.y << 5) + lane] * am);
        o.y = f2h2(Lut[(hi.x << 5) + lane] * am, Lut[(hi.y << 5) + lane] * am);
        *(uint2*)(Wp + ((size_t)nb * Kb16 + kb64 * 4 + q) * 128 + lane * 4) = o;
    }
}

__global__ __launch_bounds__(256) void dequant_w(
    const int* __restrict__ codes, const float* __restrict__ absmax,
    __half* __restrict__ Wp, int M, int K)
{
    __shared__ float Lut[512];
    for (int i = threadIdx.x; i < 512; i += 256) Lut[i] = NF4c[i >> 5];
    __syncthreads();
    int gw = (blockIdx.x * 256 + threadIdx.x) >> 5;
    dequant_body(codes, absmax, Wp, M, K, gw, threadIdx.x & 31, Lut);
}

__global__ __launch_bounds__(256) void dequant_gu(
    const int* __restrict__ cg, const float* __restrict__ amg, __half* __restrict__ Wg,
    const int* __restrict__ cu, const float* __restrict__ amu, __half* __restrict__ Wu,
    int M, int K, int nblk_half)
{
    __shared__ float Lut[512];
    for (int i = threadIdx.x; i < 512; i += 256) Lut[i] = NF4c[i >> 5];
    __syncthreads();
    int b = blockIdx.x;
    int lane = threadIdx.x & 31;
    if (b < nblk_half) {
        int gw = (b * 256 + threadIdx.x) >> 5;
        dequant_body(cg, amg, Wg, M, K, gw, lane, Lut);
    } else {
        int gw = ((b - nblk_half) * 256 + threadIdx.x) >> 5;
        dequant_body(cu, amu, Wu, M, K, gw, lane, Lut);
    }
}

// ---------------- fused gate+up GEMM + silu (BT=64, BM=256, 512 thr) ----------------
// 16 warps as 2 warpT x 8 warpM. 3-stage BK=32 cp.async pipeline.
__global__ __launch_bounds__(512, 1) void gemm_gateup(
    const __half* __restrict__ Ap,
    const __half* __restrict__ Wg,
    const __half* __restrict__ Wu,
    __half* __restrict__ outh,
    int K, int Mout)
{
    constexpr int A_ST = 4096;                    // 64 tok x 32 k fp16
    constexpr int B_ST = 16384;                   // 256 m x 32 k fp16
    constexpr int BG_OFF = 3 * A_ST;              // 12288
    constexpr int BU_OFF = BG_OFF + 3 * B_ST;     // 61440

    extern __shared__ char smem[];
    const uint32_t sb = smem_u32(smem);

    const int tid = threadIdx.x;
    const int warp = tid >> 5, lane = tid & 31;
    const int warpT = warp >> 3, warpM = warp & 7;
    const int tg = lane >> 2, tig = lane & 3;
    const int t0g = blockIdx.x * 4;
    const int m0 = blockIdx.y * 256;
    const int m0g = m0 >> 3;
    const int Kb16 = K >> 4;
    const int ktiles = K >> 5;

    float ag[2][4][4], au[2][4][4];
#pragma unroll
    for (int i = 0; i < 2; i++)
#pragma unroll
        for (int j = 0; j < 4; j++)
#pragma unroll
            for (int r = 0; r < 4; r++) { ag[i][j][r] = 0.f; au[i][j][r] = 0.f; }

    auto issue_load = [&](int kt) {
        const int s = kt % 3;
        if (tid < 256) {
            int tt = tid >> 6, kbi = (tid >> 5) & 1, ln = tid & 31;
            const __half* src = Ap + (((size_t)(t0g + tt) * Kb16 + kt * 2 + kbi) * 32 + ln) * 8;
            cpa16(sb + s * A_ST + (uint32_t)tid * 16, src);
        }
#pragma unroll
        for (int i = 0; i < 2; i++) {
            int idx = tid + i * 512;
            int kbi = idx >> 9, nb = (idx >> 4) & 31, ln2 = idx & 15;
            size_t off = ((size_t)(m0g + nb) * Kb16 + kt * 2 + kbi) * 128 + ln2 * 8;
            cpa16(sb + BG_OFF + s * B_ST + (uint32_t)idx * 16, Wg + off);
            cpa16(sb + BU_OFF + s * B_ST + (uint32_t)idx * 16, Wu + off);
        }
        asm volatile("cp.async.commit_group;" ::: "memory");
    };

    issue_load(0);
    issue_load(1);

    for (int kt = 0; kt < ktiles; kt++) {
        const int s = kt % 3;
        if (kt < ktiles - 1) CPA_WAIT(1);
        else                 CPA_WAIT(0);
        __syncthreads();

        const char* AsS = smem + s * A_ST;
        const char* BgS = smem + BG_OFF + s * B_ST;
        const char* BuS = smem + BU_OFF + s * B_ST;

#pragma unroll
        for (int kc = 0; kc < 2; kc++) {
            uint32_t a[2][4], bg[4][2], bu[4][2];
#pragma unroll
            for (int i = 0; i < 2; i++) {
                int tt = warpT * 2 + i;
                uint4 v = *(const uint4*)(AsS + ((tt * 2 + kc) * 32 + lane) * 16);
                a[i][0] = v.x; a[i][1] = v.y; a[i][2] = v.z; a[i][3] = v.w;
            }
#pragma unroll
            for (int j = 0; j < 4; j++) {
                int row = (kc * 32 + warpM * 4 + j) * 32 + lane;
                uint2 wg2 = *(const uint2*)(BgS + row * 8);
                uint2 wu2 = *(const uint2*)(BuS + row * 8);
                bg[j][0] = wg2.x; bg[j][1] = wg2.y;
                bu[j][0] = wu2.x; bu[j][1] = wu2.y;
            }
#pragma unroll
            for (int i = 0; i < 2; i++)
#pragma unroll
                for (int j = 0; j < 4; j++) {
                    MMA_H(ag[i][j], a[i], bg[j][0], bg[j][1]);
                    MMA_H(au[i][j], a[i], bu[j][0], bu[j][1]);
                }
        }

        if (kt + 2 < ktiles) issue_load(kt + 2);
    }

    // epilogue: h = silu(g)*u -> fp16, staged to permuted layout via smem
    __syncthreads();
    uint32_t* Ep = (uint32_t*)smem;   // [4 t-blk][16 m-blk][32 lanes][4 words] = 32KB
#pragma unroll
    for (int i = 0; i < 2; i++) {
#pragma unroll
        for (int j = 0; j < 4; j++) {
            float h0 = ag[i][j][0] / (1.f + __expf(-ag[i][j][0])) * au[i][j][0];
            float h1 = ag[i][j][1] / (1.f + __expf(-ag[i][j][1])) * au[i][j][1];
            float h2 = ag[i][j][2] / (1.f + __expf(-ag[i][j][2])) * au[i][j][2];
            float h3 = ag[i][j][3] / (1.f + __expf(-ag[i][j][3])) * au[i][j][3];
            int tt = warpT * 2 + i;
            int mb = warpM * 2 + (j >> 1);
            uint32_t* wptr = Ep + ((tt * 16 + mb) * 32 + lane) * 4 + (j & 1) * 2;
            wptr[0] = f2h2(h0, h1);
            wptr[1] = f2h2(h2, h3);
        }
    }
    __syncthreads();
    const int Mb16 = Mout >> 4;
    for (int idx = tid; idx < 2048; idx += 512) {
        int tt = idx >> 9, mb = (idx >> 5) & 15, ln = idx & 31;
        uint4 v = *(const uint4*)((const char*)Ep + idx * 16);
        size_t gb = (size_t)(t0g + tt) * Mb16 + (m0 >> 4) + mb;
        *(uint4*)(outh + (gb * 32 + ln) * 8) = v;
    }
}

// ---------------- down GEMM (BT=64, BM=256, 512 thr, fp32 linear out) ----------------
__global__ __launch_bounds__(512, 1) void gemm_down(
    const __half* __restrict__ Ap,
    const __half* __restrict__ Wp,
    float* __restrict__ outf,
    int K, int Mout)
{
    constexpr int A_ST  = 4096;
    constexpr int B_ST  = 16384;
    constexpr int B_OFF = 3 * A_ST;

    extern __shared__ char smem[];
    const uint32_t sb = smem_u32(smem);

    const int tid = threadIdx.x;
    const int warp = tid >> 5, lane = tid & 31;
    const int warpT = warp >> 3, warpM = warp & 7;
    const int tg = lane >> 2, tig = lane & 3;
    const int t0 = blockIdx.x * 64;
    const int m0 = blockIdx.y * 256;
    const int t0g = t0 >> 4;
    const int m0g = m0 >> 3;
    const int Kb16 = K >> 4;
    const int ktiles = K >> 5;

    float acc[2][4][4];
#pragma unroll
    for (int i = 0; i < 2; i++)
#pragma unroll
        for (int j = 0; j < 4; j++)
#pragma unroll
            for (int r = 0; r < 4; r++) acc[i][j][r] = 0.f;

    auto issue_load = [&](int kt) {
        const int s = kt % 3;
        if (tid < 256) {
            int tt = tid >> 6, kbi = (tid >> 5) & 1, ln = tid & 31;
            const __half* src = Ap + (((size_t)(t0g + tt) * Kb16 + kt * 2 + kbi) * 32 + ln) * 8;
            cpa16(sb + s * A_ST + (uint32_t)tid * 16, src);
        }
#pragma unroll
        for (int i = 0; i < 2; i++) {
            int idx = tid + i * 512;
            int kbi = idx >> 9, nb = (idx >> 4) & 31, ln2 = idx & 15;
            const __half* src = Wp + ((size_t)(m0g + nb) * Kb16 + kt * 2 + kbi) * 128 + ln2 * 8;
            cpa16(sb + B_OFF + s * B_ST + (uint32_t)idx * 16, src);
        }
        asm volatile("cp.async.commit_group;" ::: "memory");
    };

    issue_load(0);
    issue_load(1);

    for (int kt = 0; kt < ktiles; kt++) {
        const int s = kt % 3;
        if (kt < ktiles - 1) CPA_WAIT(1);
        else                 CPA_WAIT(0);
        __syncthreads();

        const char* AsS = smem + s * A_ST;
        const char* BsS = smem + B_OFF + s * B_ST;

#pragma unroll
        for (int kc = 0; kc < 2; kc++) {
            uint32_t a[2][4], b[4][2];
#pragma unroll
            for (int i = 0; i < 2; i++) {
                int tt = warpT * 2 + i;
                uint4 v = *(const uint4*)(AsS + ((tt * 2 + kc) * 32 + lane) * 16);
                a[i][0] = v.x; a[i][1] = v.y; a[i][2] = v.z; a[i][3] = v.w;
            }
#pragma unroll
            for (int j = 0; j < 4; j++) {
                uint2 w = *(const uint2*)(BsS + ((kc * 32 + warpM * 4 + j) * 32 + lane) * 8);
                b[j][0] = w.x; b[j][1] = w.y;
            }
#pragma unroll
            for (int i = 0; i < 2; i++)
#pragma unroll
                for (int j = 0; j < 4; j++)
                    MMA_H(acc[i][j], a[i], b[j][0], b[j][1]);
        }

        if (kt + 2 < ktiles) issue_load(kt + 2);
    }

#pragma unroll
    for (int i = 0; i < 2; i++) {
#pragma unroll
        for (int j = 0; j < 4; j++) {
            int t = t0 + warpT * 32 + i * 16 + tg;
            int m = m0 + warpM * 32 + j * 8 + tig * 2;
            *(float2*)&outf[(size_t)t * Mout + m] = make_float2(acc[i][j][0], acc[i][j][1]);
            *(float2*)&outf[(size_t)(t + 8) * Mout + m] = make_float2(acc[i][j][2], acc[i][j][3]);
        }
    }
}

extern "C" void kernel_launch(void* const* d_in, const int* in_sizes, int n_in,
                              void* d_out, int out_size) {
    (void)in_sizes; (void)n_in; (void)out_size;
    const float* x           = (const float*)d_in[0];
    const int*   gate_codes  = (const int*)d_in[1];
    const float* gate_absmax = (const float*)d_in[2];
    const int*   up_codes    = (const int*)d_in[3];
    const float* up_absmax   = (const float*)d_in[4];
    const int*   down_codes  = (const int*)d_in[5];
    const float* down_absmax = (const float*)d_in[6];
    float* out = (float*)d_out;

    __half *wg, *wu, *wd, *xq, *hp;
    cudaGetSymbolAddress((void**)&wg, g_wg);
    cudaGetSymbolAddress((void**)&wu, g_wu);
    cudaGetSymbolAddress((void**)&wd, g_wd);
    cudaGetSymbolAddress((void**)&xq, g_xq);
    cudaGetSymbolAddress((void**)&hp, g_hp);

    const int SM_GU = 3 * 4096 + 6 * 16384;  // 110592
    const int SM_DN = 3 * 4096 + 3 * 16384;  // 61440
    cudaFuncSetAttribute((const void*)gemm_gateup, cudaFuncAttributeMaxDynamicSharedMemorySize, SM_GU);
    cudaFuncSetAttribute((const void*)gemm_down, cudaFuncAttributeMaxDynamicSharedMemorySize, SM_DN);

    // Persistent side-stream + events (host resources, created once)
    static cudaStream_t s2 = nullptr;
    static cudaEvent_t eF = nullptr, eJ = nullptr;
    if (s2 == nullptr) {
        cudaStreamCreateWithFlags(&s2, cudaStreamNonBlocking);
        cudaEventCreateWithFlags(&eF, cudaEventDisableTiming);
        cudaEventCreateWithFlags(&eJ, cudaEventDisableTiming);
    }

    const int nblk1 = ((MDIM / 8) * (HD / 64) * 32 + 255) / 256;   // 11008
    const int nblk2 = ((HD / 8) * (MDIM / 64) * 32 + 255) / 256;   // 11008

    {
        int nwarps = (TOK / 16) * (HD / 16);
        permute_xh<<<(nwarps * 32 + 255) / 256, 256>>>(x, xq, TOK, HD);
    }
    dequant_gu<<<2 * nblk1, 256>>>(gate_codes, gate_absmax, wg,
                                   up_codes, up_absmax, wu, MDIM, HD, nblk1);

    // fork: down dequant on s2 overlaps gemm_gateup on the main stream
    cudaEventRecord(eF, 0);
    cudaStreamWaitEvent(s2, eF, 0);
    dequant_w<<<nblk2, 256, 0, s2>>>(down_codes, down_absmax, wd, HD, MDIM);
    cudaEventRecord(eJ, s2);

    dim3 grid1(TOK / 64, MDIM / 256);    // (8, 43)
    gemm_gateup<<<grid1, 512, SM_GU>>>(xq, wg, wu, hp, HD, MDIM);

    cudaStreamWaitEvent(0, eJ, 0);
    dim3 grid2(TOK / 64, HD / 256);      // (8, 16)
    gemm_down<<<grid2, 512, SM_DN>>>(hp, wd, out, MDIM, HD);
}

// round 15
// speedup vs baseline: 1.3652x; 1.3652x over previous
#include <cuda_runtime.h>
#include <cuda_fp16.h>
#include <cstdint>

// Problem dims (fixed by dataset)
#define HD    4096
#define MDIM  11008
#define TOK   512

__constant__ float NF4c[16] = {
    -1.0f, -0.6961928009986877f, -0.5250730514526367f, -0.39491748809814453f,
    -0.28444138169288635f, -0.18477343022823334f, -0.09105003625154495f, 0.0f,
    0.07958029955625534f, 0.16093020141124725f, 0.24611230194568634f,
    0.33791524171829224f, 0.44070982933044434f, 0.5626170039176941f,
    0.7229568362236023f, 1.0f};

// Static device scratch
__device__ __half g_wg[(size_t)MDIM * HD];   // gate W fp16, B-frag permuted
__device__ __half g_wu[(size_t)MDIM * HD];   // up   W fp16, B-frag permuted
__device__ __half g_wd[(size_t)HD * MDIM];   // down W fp16, B-frag permuted
__device__ __half g_xq[(size_t)TOK * HD];    // x fp16, A-frag permuted
__device__ __half g_hp[(size_t)TOK * MDIM];  // h fp16, A-frag permuted

__device__ __forceinline__ void cpa16(uint32_t dst, const void* src) {
    asm volatile("cp.async.cg.shared.global [%0], [%1], 16;" :: "r"(dst), "l"(src));
}
__device__ __forceinline__ uint32_t smem_u32(const void* p) {
    uint32_t a;
    asm("{ .reg .u64 t; cvta.to.shared.u64 t, %1; cvt.u32.u64 %0, t; }" : "=r"(a) : "l"(p));
    return a;
}
__device__ __forceinline__ uint32_t f2h2(float lo, float hi) {
    uint32_t r;
    asm("cvt.rn.f16x2.f32 %0, %2, %1;" : "=r"(r) : "f"(lo), "f"(hi));
    return r;
}
#define MMA_H(acc, a, b0, b1) \
    asm volatile( \
        "mma.sync.aligned.m16n8k16.row.col.f32.f16.f16.f32 " \
        "{%0,%1,%2,%3}, {%4,%5,%6,%7}, {%8,%9}, {%0,%1,%2,%3};" \
        : "+f"(acc[0]), "+f"(acc[1]), "+f"(acc[2]), "+f"(acc[3]) \
        : "r"(a[0]), "r"(a[1]), "r"(a[2]), "r"(a[3]), "r"(b0), "r"(b1))

#define CPA_WAIT(N) asm volatile("cp.async.wait_group %0;" :: "n"(N) : "memory")

// ---------------- permute x -> fp16 A-fragment layout ----------------
__global__ void permute_xh(const float* __restrict__ X, __half* __restrict__ Xp, int T, int K) {
    int gw = (blockIdx.x * blockDim.x + threadIdx.x) >> 5;
    int lane = threadIdx.x & 31;
    int kb16 = K >> 4;
    if (gw >= (T >> 4) * kb16) return;
    int tb = gw / kb16, kb = gw % kb16;
    int tg = lane >> 2, tig = lane & 3;
    const float* p0 = X + (size_t)(tb * 16 + tg) * K + kb * 16 + tig * 2;
    const float* p1 = p0 + (size_t)8 * K;
    float2 v00 = *(const float2*)p0;
    float2 v10 = *(const float2*)p1;
    float2 v01 = *(const float2*)(p0 + 8);
    float2 v11 = *(const float2*)(p1 + 8);
    uint4 o;
    o.x = f2h2(v00.x, v00.y);
    o.y = f2h2(v10.x, v10.y);
    o.z = f2h2(v01.x, v01.y);
    o.w = f2h2(v11.x, v11.y);
    *(uint4*)(Xp + ((size_t)gw * 32 + lane) * 8) = o;
}

// ---------------- dequant NF4 int32 codes -> fp16 W in B-frag layout ----------------
__device__ __forceinline__ void dequant_body(
    const int* __restrict__ codes, const float* __restrict__ absmax,
    __half* __restrict__ Wp, int M, int K, int gw, int lane, const float* Lut)
{
    int Kb64 = K >> 6, Kb16 = K >> 4;
    if (gw >= (M >> 3) * Kb64) return;
    int nb = gw / Kb64, kb64 = gw % Kb64;
    int n = lane >> 2, tig = lane & 3;
    int m = nb * 8 + n;
    float am = absmax[(size_t)m * Kb64 + kb64];
    const int* rp = codes + (size_t)m * K + (size_t)kb64 * 64;
#pragma unroll
    for (int q = 0; q < 4; q++) {
        int2 lo = *(const int2*)(rp + q * 16 + tig * 2);
        int2 hi = *(const int2*)(rp + q * 16 + tig * 2 + 8);
        uint2 o;
        o.x = f2h2(Lut[(lo.x << 5) + lane] * am, Lut[(lo.y << 5) + lane] * am);
        o.y = f2h2(Lut[(hi.x << 5) + lane] * am, Lut[(hi.y << 5) + lane] * am);
        *(uint2*)(Wp + ((size_t)nb * Kb16 + kb64 * 4 + q) * 128 + lane * 4) = o;
    }
}

__global__ __launch_bounds__(256) void dequant_w(
    const int* __restrict__ codes, const float* __restrict__ absmax,
    __half* __restrict__ Wp, int M, int K)
{
    __shared__ float Lut[512];
    for (int i = threadIdx.x; i < 512; i += 256) Lut[i] = NF4c[i >> 5];
    __syncthreads();
    int gw = (blockIdx.x * 256 + threadIdx.x) >> 5;
    dequant_body(codes, absmax, Wp, M, K, gw, threadIdx.x & 31, Lut);
}

__global__ __launch_bounds__(256) void dequant_gu(
    const int* __restrict__ cg, const float* __restrict__ amg, __half* __restrict__ Wg,
    const int* __restrict__ cu, const float* __restrict__ amu, __half* __restrict__ Wu,
    int M, int K, int nblk_half)
{
    __shared__ float Lut[512];
    for (int i = threadIdx.x; i < 512; i += 256) Lut[i] = NF4c[i >> 5];
    __syncthreads();
    int b = blockIdx.x;
    int lane = threadIdx.x & 31;
    if (b < nblk_half) {
        int gw = (b * 256 + threadIdx.x) >> 5;
        dequant_body(cg, amg, Wg, M, K, gw, lane, Lut);
    } else {
        int gw = ((b - nblk_half) * 256 + threadIdx.x) >> 5;
        dequant_body(cu, amu, Wu, M, K, gw, lane, Lut);
    }
}

// ---------------- fused gate+up GEMM + silu (R8/R10 proven config) ----------------
// BT=64, BM=128, 4-stage cp.async (<=2 outstanding), grid = (t fast, m slow).
__global__ __launch_bounds__(256, 2) void gemm_gateup(
    const __half* __restrict__ Ap,
    const __half* __restrict__ Wg,
    const __half* __restrict__ Wu,
    __half* __restrict__ outh,
    int K, int Mout)
{
    constexpr int A_ST = 4096;
    constexpr int BG_OFF = 4 * A_ST;
    constexpr int BU_OFF = BG_OFF + 4 * 8192;

    extern __shared__ char smem[];
    const uint32_t sb = smem_u32(smem);

    const int tid = threadIdx.x;
    const int warp = tid >> 5, lane = tid & 31;
    const int warpT = warp >> 2, warpM = warp & 3;
    const int tg = lane >> 2, tig = lane & 3;
    const int t0g = blockIdx.x * 4;
    const int m0 = blockIdx.y * 128;
    const int m0g = m0 >> 3;
    const int Kb16 = K >> 4;
    const int ktiles = K >> 5;

    float ag[2][4][4], au[2][4][4];
#pragma unroll
    for (int i = 0; i < 2; i++)
#pragma unroll
        for (int j = 0; j < 4; j++)
#pragma unroll
            for (int r = 0; r < 4; r++) { ag[i][j][r] = 0.f; au[i][j][r] = 0.f; }

    auto issue_load = [&](int kt) {
        const int s = kt & 3;
        {
            int tt = tid >> 6, kbi = (tid >> 5) & 1, ln = tid & 31;
            const __half* src = Ap + (((size_t)(t0g + tt) * Kb16 + kt * 2 + kbi) * 32 + ln) * 8;
            cpa16(sb + s * A_ST + (uint32_t)tid * 16, src);
        }
#pragma unroll
        for (int i = 0; i < 2; i++) {
            int idx = tid + i * 256;
            int kbi = idx >> 8, nb = (idx >> 4) & 15, ln2 = idx & 15;
            size_t off = ((size_t)(m0g + nb) * Kb16 + kt * 2 + kbi) * 128 + ln2 * 8;
            cpa16(sb + BG_OFF + s * 8192 + (uint32_t)idx * 16, Wg + off);
            cpa16(sb + BU_OFF + s * 8192 + (uint32_t)idx * 16, Wu + off);
        }
        asm volatile("cp.async.commit_group;" ::: "memory");
    };

    issue_load(0);
    issue_load(1);
    issue_load(2);

    for (int kt = 0; kt < ktiles; kt++) {
        const int s = kt & 3;
        if (kt < ktiles - 2)      CPA_WAIT(2);
        else if (kt < ktiles - 1) CPA_WAIT(1);
        else                      CPA_WAIT(0);
        __syncthreads();

        const char* AsS = smem + s * A_ST;
        const char* BgS = smem + BG_OFF + s * 8192;
        const char* BuS = smem + BU_OFF + s * 8192;

#pragma unroll
        for (int kc = 0; kc < 2; kc++) {
            uint32_t a[2][4], bg[4][2], bu[4][2];
#pragma unroll
            for (int i = 0; i < 2; i++) {
                int tt = warpT * 2 + i;
                uint4 v = *(const uint4*)(AsS + ((tt * 2 + kc) * 32 + lane) * 16);
                a[i][0] = v.x; a[i][1] = v.y; a[i][2] = v.z; a[i][3] = v.w;
            }
#pragma unroll
            for (int j = 0; j < 4; j++) {
                int row = (kc * 16 + warpM * 4 + j) * 32 + lane;
                uint2 wg2 = *(const uint2*)(BgS + row * 8);
                uint2 wu2 = *(const uint2*)(BuS + row * 8);
                bg[j][0] = wg2.x; bg[j][1] = wg2.y;
                bu[j][0] = wu2.x; bu[j][1] = wu2.y;
            }
#pragma unroll
            for (int i = 0; i < 2; i++)
#pragma unroll
                for (int j = 0; j < 4; j++) {
                    MMA_H(ag[i][j], a[i], bg[j][0], bg[j][1]);
                    MMA_H(au[i][j], a[i], bu[j][0], bu[j][1]);
                }
        }

        if (kt + 3 < ktiles) issue_load(kt + 3);
    }

    // epilogue: h = silu(g)*u -> fp16, staged to permuted layout via smem
    __syncthreads();
    uint32_t* Ep = (uint32_t*)smem;
#pragma unroll
    for (int i = 0; i < 2; i++) {
#pragma unroll
        for (int j = 0; j < 4; j++) {
            float h0 = ag[i][j][0] / (1.f + __expf(-ag[i][j][0])) * au[i][j][0];
            float h1 = ag[i][j][1] / (1.f + __expf(-ag[i][j][1])) * au[i][j][1];
            float h2 = ag[i][j][2] / (1.f + __expf(-ag[i][j][2])) * au[i][j][2];
            float h3 = ag[i][j][3] / (1.f + __expf(-ag[i][j][3])) * au[i][j][3];
            int tt = warpT * 2 + i;
            int mb = warpM * 2 + (j >> 1);
            uint32_t* wptr = Ep + ((tt * 8 + mb) * 32 + lane) * 4 + (j & 1) * 2;
            wptr[0] = f2h2(h0, h1);
            wptr[1] = f2h2(h2, h3);
        }
    }
    __syncthreads();
    const int Mb16 = Mout >> 4;
    for (int idx = tid; idx < 1024; idx += 256) {
        int tt = idx >> 8, mb = (idx >> 5) & 7, ln = idx & 31;
        uint4 v = *(const uint4*)((const char*)Ep + idx * 16);
        size_t gb = (size_t)(t0g + tt) * Mb16 + (m0 >> 4) + mb;
        *(uint4*)(outh + (gb * 32 + ln) * 8) = v;
    }
}

// ---------------- down GEMM (R8/R10 proven config) ----------------
__global__ __launch_bounds__(256, 2) void gemm_down(
    const __half* __restrict__ Ap,
    const __half* __restrict__ Wp,
    float* __restrict__ outf,
    int K, int Mout)
{
    constexpr int A_ST  = 4096;
    constexpr int B_OFF = 4 * A_ST;

    extern __shared__ char smem[];
    const uint32_t sb = smem_u32(smem);

    const int tid = threadIdx.x;
    const int warp = tid >> 5, lane = tid & 31;
    const int warpT = warp >> 2, warpM = warp & 3;
    const int tg = lane >> 2, tig = lane & 3;
    const int t0 = blockIdx.x * 64;
    const int m0 = blockIdx.y * 128;
    const int t0g = t0 >> 4;
    const int m0g = m0 >> 3;
    const int Kb16 = K >> 4;
    const int ktiles = K >> 5;

    float acc[2][4][4];
#pragma unroll
    for (int i = 0; i < 2; i++)
#pragma unroll
        for (int j = 0; j < 4; j++)
#pragma unroll
            for (int r = 0; r < 4; r++) acc[i][j][r] = 0.f;

    auto issue_load = [&](int kt) {
        const int s = kt & 3;
        {
            int tt = tid >> 6, kbi = (tid >> 5) & 1, ln = tid & 31;
            const __half* src = Ap + (((size_t)(t0g + tt) * Kb16 + kt * 2 + kbi) * 32 + ln) * 8;
            cpa16(sb + s * A_ST + (uint32_t)tid * 16, src);
        }
#pragma unroll
        for (int i = 0; i < 2; i++) {
            int idx = tid + i * 256;
            int kbi = idx >> 8, nb = (idx >> 4) & 15, ln2 = idx & 15;
            const __half* src = Wp + ((size_t)(m0g + nb) * Kb16 + kt * 2 + kbi) * 128 + ln2 * 8;
            cpa16(sb + B_OFF + s * 8192 + (uint32_t)idx * 16, src);
        }
        asm volatile("cp.async.commit_group;" ::: "memory");
    };

    issue_load(0);
    issue_load(1);
    issue_load(2);

    for (int kt = 0; kt < ktiles; kt++) {
        const int s = kt & 3;
        if (kt < ktiles - 2)      CPA_WAIT(2);
        else if (kt < ktiles - 1) CPA_WAIT(1);
        else                      CPA_WAIT(0);
        __syncthreads();

        const char* AsS = smem + s * A_ST;
        const char* BsS = smem + B_OFF + s * 8192;

#pragma unroll
        for (int kc = 0; kc < 2; kc++) {
            uint32_t a[2][4], b[4][2];
#pragma unroll
            for (int i = 0; i < 2; i++) {
                int tt = warpT * 2 + i;
                uint4 v = *(const uint4*)(AsS + ((tt * 2 + kc) * 32 + lane) * 16);
                a[i][0] = v.x; a[i][1] = v.y; a[i][2] = v.z; a[i][3] = v.w;
            }
#pragma unroll
            for (int j = 0; j < 4; j++) {
                uint2 w = *(const uint2*)(BsS + ((kc * 16 + warpM * 4 + j) * 32 + lane) * 8);
                b[j][0] = w.x; b[j][1] = w.y;
            }
#pragma unroll
            for (int i = 0; i < 2; i++)
#pragma unroll
                for (int j = 0; j < 4; j++)
                    MMA_H(acc[i][j], a[i], b[j][0], b[j][1]);
        }

        if (kt + 3 < ktiles) issue_load(kt + 3);
    }

#pragma unroll
    for (int i = 0; i < 2; i++) {
#pragma unroll
        for (int j = 0; j < 4; j++) {
            int t = t0 + warpT * 32 + i * 16 + tg;
            int m = m0 + warpM * 32 + j * 8 + tig * 2;
            *(float2*)&outf[(size_t)t * Mout + m] = make_float2(acc[i][j][0], acc[i][j][1]);
            *(float2*)&outf[(size_t)(t + 8) * Mout + m] = make_float2(acc[i][j][2], acc[i][j][3]);
        }
    }
}

extern "C" void kernel_launch(void* const* d_in, const int* in_sizes, int n_in,
                              void* d_out, int out_size) {
    (void)in_sizes; (void)n_in; (void)out_size;
    const float* x           = (const float*)d_in[0];
    const int*   gate_codes  = (const int*)d_in[1];
    const float* gate_absmax = (const float*)d_in[2];
    const int*   up_codes    = (const int*)d_in[3];
    const float* up_absmax   = (const float*)d_in[4];
    const int*   down_codes  = (const int*)d_in[5];
    const float* down_absmax = (const float*)d_in[6];
    float* out = (float*)d_out;

    __half *wg, *wu, *wd, *xq, *hp;
    cudaGetSymbolAddress((void**)&wg, g_wg);
    cudaGetSymbolAddress((void**)&wu, g_wu);
    cudaGetSymbolAddress((void**)&wd, g_wd);
    cudaGetSymbolAddress((void**)&xq, g_xq);
    cudaGetSymbolAddress((void**)&hp, g_hp);

    const int SM_GU = 4 * 4096 + 8 * 8192;  // 81920
    const int SM_DN = 4 * 4096 + 4 * 8192;  // 49152
    cudaFuncSetAttribute((const void*)gemm_gateup, cudaFuncAttributeMaxDynamicSharedMemorySize, SM_GU);
    cudaFuncSetAttribute((const void*)gemm_down, cudaFuncAttributeMaxDynamicSharedMemorySize, SM_DN);

    // Persistent streams with priorities + events (host resources, created once)
    static cudaStream_t sHi = nullptr, sLo = nullptr;
    static cudaEvent_t eF = nullptr, eG = nullptr, eJ = nullptr;
    if (sHi == nullptr) {
        int prLeast = 0, prGreatest = 0;
        cudaDeviceGetStreamPriorityRange(&prLeast, &prGreatest);
        cudaStreamCreateWithPriority(&sHi, cudaStreamNonBlocking, prGreatest); // highest
        cudaStreamCreateWithPriority(&sLo, cudaStreamNonBlocking, prLeast);    // lowest
        cudaEventCreateWithFlags(&eF, cudaEventDisableTiming);
        cudaEventCreateWithFlags(&eG, cudaEventDisableTiming);
        cudaEventCreateWithFlags(&eJ, cudaEventDisableTiming);
    }

    const int nblk1 = ((MDIM / 8) * (HD / 64) * 32 + 255) / 256;   // 11008
    const int nblk2 = ((HD / 8) * (MDIM / 64) * 32 + 255) / 256;   // 11008

    // main (capture) stream: permute + gate/up dequant
    {
        int nwarps = (TOK / 16) * (HD / 16);
        permute_xh<<<(nwarps * 32 + 255) / 256, 256>>>(x, xq, TOK, HD);
    }
    dequant_gu<<<2 * nblk1, 256>>>(gate_codes, gate_absmax, wg,
                                   up_codes, up_absmax, wu, MDIM, HD, nblk1);
    cudaEventRecord(eF, 0);

    // HIGH priority, enqueued FIRST: gateup gets SM slots preferentially
    cudaStreamWaitEvent(sHi, eF, 0);
    dim3 grid1(TOK / 64, MDIM / 128);    // (8, 86) — t fast, m slow (L2 W reuse)
    gemm_gateup<<<grid1, 256, SM_GU, sHi>>>(xq, wg, wu, hp, HD, MDIM);
    cudaEventRecord(eG, sHi);

    // LOW priority, enqueued second: dequant_wd fills idle SMs in gateup's tail
    cudaStreamWaitEvent(sLo, eF, 0);
    dequant_w<<<nblk2, 256, 0, sLo>>>(down_codes, down_absmax, wd, HD, MDIM);
    cudaEventRecord(eJ, sLo);

    // join on main: down GEMM needs hp (sHi) and wd (sLo)
    cudaStreamWaitEvent(0, eG, 0);
    cudaStreamWaitEvent(0, eJ, 0);
    dim3 grid2(TOK / 64, HD / 128);      // (8, 32)
    gemm_down<<<grid2, 256, SM_DN>>>(hp, wd, out, MDIM, HD);
}